// round 1
// baseline (speedup 1.0000x reference)
#include <cuda_runtime.h>

#define B_  4
#define Q_  512
#define KK_ 1024
#define D_  512
#define H_  128
#define DV_ 512

// Scratch (device globals; no allocation allowed in kernel_launch)
__device__ float g_qp[B_ * Q_ * H_];      // 1 MB
__device__ float g_kp[B_ * KK_ * H_];     // 2 MB
__device__ float g_attn[B_ * Q_ * KK_];   // 8 MB

__device__ __forceinline__ float tanh_fast(float x) {
    float y;
    asm("tanh.approx.f32 %0, %1;" : "=f"(y) : "f"(x));
    return y;
}

// ----------------------------------------------------------------------------
// Kernel 1: projections. C[row, h] = sum_d A[row, d] * W[d, h]
// blocks [0,64): qp (2048 rows), [64,192): kp (4096 rows). BM=32, BK=16.
// 256 threads: tx = col/4 (32 groups * 4 cols = 128), ty = row group (8 * 4 rows)
// ----------------------------------------------------------------------------
__global__ __launch_bounds__(256) void proj_kernel(
    const float* __restrict__ Aq, const float* __restrict__ Ak,
    const float* __restrict__ Wq, const float* __restrict__ Wk)
{
    __shared__ float As[32][16];
    __shared__ float Ws[16][128];

    int blk = blockIdx.x;
    const float* A;
    const float* W;
    float* C;
    int rowbase;
    if (blk < 64) { A = Aq; W = Wq; C = g_qp; rowbase = blk * 32; }
    else          { A = Ak; W = Wk; C = g_kp; rowbase = (blk - 64) * 32; }

    int tid = threadIdx.x;
    int tx = tid & 31;
    int ty = tid >> 5;            // warp id == ty -> a-loads are broadcast

    float acc[4][4];
#pragma unroll
    for (int i = 0; i < 4; i++)
#pragma unroll
        for (int j = 0; j < 4; j++) acc[i][j] = 0.f;

    int lr = tid >> 3;            // A-tile load row (0..31)
    int lc = (tid & 7) << 1;      // A-tile load col (float2)

    for (int kk = 0; kk < D_; kk += 16) {
        float2 av = *(const float2*)(A + (size_t)(rowbase + lr) * D_ + kk + lc);
        As[lr][lc]     = av.x;
        As[lr][lc + 1] = av.y;
#pragma unroll
        for (int rep = 0; rep < 2; rep++) {
            int idx = tid + rep * 256;          // float4 index in [0,512)
            int r = idx >> 5, c = (idx & 31) << 2;
            *(float4*)(&Ws[r][c]) = *(const float4*)(W + (size_t)(kk + r) * H_ + c);
        }
        __syncthreads();
#pragma unroll
        for (int k = 0; k < 16; k++) {
            float a0 = As[ty * 4 + 0][k];
            float a1 = As[ty * 4 + 1][k];
            float a2 = As[ty * 4 + 2][k];
            float a3 = As[ty * 4 + 3][k];
            float4 bv = *(float4*)(&Ws[k][tx * 4]);
            acc[0][0] += a0 * bv.x; acc[0][1] += a0 * bv.y; acc[0][2] += a0 * bv.z; acc[0][3] += a0 * bv.w;
            acc[1][0] += a1 * bv.x; acc[1][1] += a1 * bv.y; acc[1][2] += a1 * bv.z; acc[1][3] += a1 * bv.w;
            acc[2][0] += a2 * bv.x; acc[2][1] += a2 * bv.y; acc[2][2] += a2 * bv.z; acc[2][3] += a2 * bv.w;
            acc[3][0] += a3 * bv.x; acc[3][1] += a3 * bv.y; acc[3][2] += a3 * bv.z; acc[3][3] += a3 * bv.w;
        }
        __syncthreads();
    }

#pragma unroll
    for (int i = 0; i < 4; i++) {
        float4 v = make_float4(acc[i][0], acc[i][1], acc[i][2], acc[i][3]);
        *(float4*)(C + (size_t)(rowbase + ty * 4 + i) * H_ + tx * 4) = v;
    }
}

// ----------------------------------------------------------------------------
// Kernel 2: scores + softmax.
// Block: 128 threads = 4 warps, warp w owns q-row (q0 + w). Grid = B*Q/4 = 512.
// k processed in 32-wide chunks: lane l owns k = chunk*32 + l.
// kp chunk staged in smem with row stride 132 floats (conflict-free LDS.128).
// ----------------------------------------------------------------------------
__global__ __launch_bounds__(128) void score_softmax_kernel(const float* __restrict__ wv_g)
{
    __shared__ float kp_sm[32 * 132];
    __shared__ float q_sm[4 * 128];
    __shared__ float w_sm[128];
    __shared__ float sc[4][1024];

    int tid = threadIdx.x;
    int w = tid >> 5;
    int l = tid & 31;

    int qb = blockIdx.x * 4;    // flattened (b,q) row base
    int b  = qb >> 9;           // / 512
    int q0 = qb & 511;

    // stage 4 q-rows + w_v
    {
        int r = tid >> 5, c = (tid & 31) << 2;
        *(float4*)&q_sm[r * 128 + c] =
            *(const float4*)&g_qp[(size_t)(b * Q_ + q0 + r) * H_ + c];
        if (tid < 32) *(float4*)&w_sm[tid * 4] = *(const float4*)&wv_g[tid * 4];
    }

    const float* kp_base = g_kp + (size_t)b * KK_ * H_;

    for (int ch = 0; ch < 32; ch++) {
        __syncthreads();   // also guards q_sm/w_sm staging on first iteration
        // stage 32 kp rows: 1024 float4 by 128 threads
#pragma unroll
        for (int i = 0; i < 8; i++) {
            int idx = tid + i * 128;
            int r = idx >> 5, cc = (idx & 31) << 2;
            *(float4*)&kp_sm[r * 132 + cc] =
                *(const float4*)&kp_base[(size_t)(ch * 32 + r) * H_ + cc];
        }
        __syncthreads();

        const float4* kr = (const float4*)&kp_sm[l * 132];   // 132/4 = 33 float4 stride
        const float4* qr = (const float4*)&q_sm[w * 128];
        const float4* wr = (const float4*)w_sm;
        float s0 = 0.f, s1 = 0.f, s2 = 0.f, s3 = 0.f;
#pragma unroll
        for (int h = 0; h < 32; h++) {
            float4 kv = kr[h];
            float4 qv = qr[h];
            float4 wv = wr[h];
            s0 += wv.x * tanh_fast(qv.x + kv.x);
            s1 += wv.y * tanh_fast(qv.y + kv.y);
            s2 += wv.z * tanh_fast(qv.z + kv.z);
            s3 += wv.w * tanh_fast(qv.w + kv.w);
        }
        sc[w][ch * 32 + l] = (s0 + s1) + (s2 + s3);
    }

    // softmax over sc[w][0..1023] (warp-private row, no block sync needed)
    float m = -1e30f;
    for (int k = l; k < 1024; k += 32) m = fmaxf(m, sc[w][k]);
#pragma unroll
    for (int o = 16; o; o >>= 1) m = fmaxf(m, __shfl_xor_sync(0xffffffffu, m, o));
    float sum = 0.f;
    for (int k = l; k < 1024; k += 32) sum += __expf(sc[w][k] - m);
#pragma unroll
    for (int o = 16; o; o >>= 1) sum += __shfl_xor_sync(0xffffffffu, sum, o);
    float inv = 1.0f / sum;

    float* arow = g_attn + (size_t)(b * Q_ + q0 + w) * KK_;
    for (int k = l; k < 1024; k += 32) arow[k] = __expf(sc[w][k] - m) * inv;
}

// ----------------------------------------------------------------------------
// Kernel 3: out[b] = attn[b] @ values[b].  M=512, N=512, Kd=1024 per batch.
// BM=BN=64, BK=16, 256 threads, 4x4 micro-tile. Grid (8, 8, 4).
// ----------------------------------------------------------------------------
__global__ __launch_bounds__(256) void av_gemm_kernel(
    const float* __restrict__ values, float* __restrict__ out)
{
    __shared__ float As[64][17];   // [row][k], pad 17 to dodge bank conflicts
    __shared__ float Bs[16][64];   // [k][col]

    int b  = blockIdx.z;
    int mb = blockIdx.y * 64;
    int nb = blockIdx.x * 64;

    const float* Ab = g_attn + (size_t)b * Q_ * KK_;     // [512,1024]
    const float* Bb = values + (size_t)b * KK_ * DV_;    // [1024,512]
    float* Ob = out + (size_t)b * Q_ * DV_;

    int tid = threadIdx.x;
    int tx = tid & 15;     // col group: cols nb + tx*4 .. +3
    int ty = tid >> 4;     // row group: rows mb + ty*4 .. +3

    float acc[4][4];
#pragma unroll
    for (int i = 0; i < 4; i++)
#pragma unroll
        for (int j = 0; j < 4; j++) acc[i][j] = 0.f;

    int ar = tid >> 2;          // A-tile load row 0..63
    int ac = (tid & 3) << 2;    // A-tile load col (float4)
    int br = tid >> 4;          // B-tile load row 0..15
    int bc = (tid & 15) << 2;   // B-tile load col (float4)

    for (int kk = 0; kk < KK_; kk += 16) {
        float4 av = *(const float4*)(Ab + (size_t)(mb + ar) * KK_ + kk + ac);
        As[ar][ac + 0] = av.x;
        As[ar][ac + 1] = av.y;
        As[ar][ac + 2] = av.z;
        As[ar][ac + 3] = av.w;
        *(float4*)(&Bs[br][bc]) = *(const float4*)(Bb + (size_t)(kk + br) * DV_ + nb + bc);
        __syncthreads();
#pragma unroll
        for (int k = 0; k < 16; k++) {
            float a0 = As[ty * 4 + 0][k];
            float a1 = As[ty * 4 + 1][k];
            float a2 = As[ty * 4 + 2][k];
            float a3 = As[ty * 4 + 3][k];
            float4 bv = *(float4*)(&Bs[k][tx * 4]);
            acc[0][0] += a0 * bv.x; acc[0][1] += a0 * bv.y; acc[0][2] += a0 * bv.z; acc[0][3] += a0 * bv.w;
            acc[1][0] += a1 * bv.x; acc[1][1] += a1 * bv.y; acc[1][2] += a1 * bv.z; acc[1][3] += a1 * bv.w;
            acc[2][0] += a2 * bv.x; acc[2][1] += a2 * bv.y; acc[2][2] += a2 * bv.z; acc[2][3] += a2 * bv.w;
            acc[3][0] += a3 * bv.x; acc[3][1] += a3 * bv.y; acc[3][2] += a3 * bv.z; acc[3][3] += a3 * bv.w;
        }
        __syncthreads();
    }

#pragma unroll
    for (int i = 0; i < 4; i++) {
        float4 v = make_float4(acc[i][0], acc[i][1], acc[i][2], acc[i][3]);
        *(float4*)(Ob + (size_t)(mb + ty * 4 + i) * DV_ + nb + tx * 4) = v;
    }
}

// ----------------------------------------------------------------------------
extern "C" void kernel_launch(void* const* d_in, const int* in_sizes, int n_in,
                              void* d_out, int out_size)
{
    const float* queries = (const float*)d_in[0];  // [4,512,512]
    const float* keys    = (const float*)d_in[1];  // [4,1024,512]
    const float* values  = (const float*)d_in[2];  // [4,1024,512]
    const float* W_q     = (const float*)d_in[3];  // [512,128]
    const float* W_k     = (const float*)d_in[4];  // [512,128]
    const float* w_v     = (const float*)d_in[5];  // [128]
    float* out = (float*)d_out;                    // [4,512,512]

    proj_kernel<<<192, 256>>>(queries, keys, W_q, W_k);
    score_softmax_kernel<<<512, 128>>>(w_v);
    dim3 g3(8, 8, 4);
    av_gemm_kernel<<<g3, 256>>>(values, out);
}

// round 2
// speedup vs baseline: 1.1989x; 1.1989x over previous
#include <cuda_runtime.h>

#define B_  4
#define Q_  512
#define KK_ 1024
#define D_  512
#define H_  128
#define DV_ 512

// Scratch (device globals; no allocation allowed in kernel_launch)
__device__ float g_qp[B_ * Q_ * H_];      // 1 MB
__device__ float g_kp[B_ * KK_ * H_];     // 2 MB
__device__ float g_attn[B_ * Q_ * KK_];   // 8 MB

__device__ __forceinline__ float tanh_fast(float x) {
    float y;
    asm("tanh.approx.f32 %0, %1;" : "=f"(y) : "f"(x));
    return y;
}

// ---- packed f32x2 helpers (sm_103a: FFMA2 reachable only via PTX) ----
__device__ __forceinline__ unsigned long long bcast2(float a) {
    unsigned long long r;
    asm("mov.b64 %0, {%1, %1};" : "=l"(r) : "f"(a));
    return r;
}
__device__ __forceinline__ void fma2(unsigned long long& d,
                                     unsigned long long a, unsigned long long b) {
    asm("fma.rn.f32x2 %0, %1, %2, %3;" : "=l"(d) : "l"(a), "l"(b), "l"(d));
}
__device__ __forceinline__ float2 unpack2(unsigned long long v) {
    float2 f;
    asm("mov.b64 {%0, %1}, %2;" : "=f"(f.x), "=f"(f.y) : "l"(v));
    return f;
}

// ---- cp.async helpers ----
__device__ __forceinline__ void cp_async16(void* smem, const void* gmem) {
    unsigned saddr = (unsigned)__cvta_generic_to_shared(smem);
    asm volatile("cp.async.cg.shared.global [%0], [%1], 16;\n" :: "r"(saddr), "l"(gmem));
}
__device__ __forceinline__ void cp_commit() {
    asm volatile("cp.async.commit_group;\n");
}
template<int N> __device__ __forceinline__ void cp_wait() {
    asm volatile("cp.async.wait_group %0;\n" :: "n"(N));
}

// ----------------------------------------------------------------------------
// Kernel 1: projections. C[row, h] = sum_d A[row, d] * W[d, h]
// blocks [0,64): qp (2048 rows), [64,192): kp (4096 rows). BM=32, BK=32.
// 256 threads, micro-tile 4 rows x 4 cols (2 f32x2 pairs). Double-buffered.
// ----------------------------------------------------------------------------
__global__ __launch_bounds__(256) void proj_kernel(
    const float* __restrict__ Aq, const float* __restrict__ Ak,
    const float* __restrict__ Wq, const float* __restrict__ Wk)
{
    __shared__ float As[2][32 * 32];
    __shared__ float Ws[2][32 * 128];

    int blk = blockIdx.x;
    const float* A;
    const float* W;
    float* C;
    int rowbase;
    if (blk < 64) { A = Aq; W = Wq; C = g_qp; rowbase = blk * 32; }
    else          { A = Ak; W = Wk; C = g_kp; rowbase = (blk - 64) * 32; }

    int tid = threadIdx.x;
    int tx = tid & 31;            // col group: tx*4 .. +3
    int ty = tid >> 5;            // row group: ty*4 .. +3

    unsigned long long acc[4][2];
#pragma unroll
    for (int i = 0; i < 4; i++) { acc[i][0] = 0ull; acc[i][1] = 0ull; }

    int ar = tid >> 3, ac = (tid & 7) << 2;      // A tile: 1 float4 per thread

    // stage helper inlined
#define PROJ_STAGE(kk, buf)                                                     \
    do {                                                                        \
        cp_async16(&As[buf][ar * 32 + ac],                                      \
                   A + (size_t)(rowbase + ar) * D_ + (kk) + ac);                \
        _Pragma("unroll")                                                       \
        for (int i_ = 0; i_ < 4; i_++) {                                        \
            int idx_ = tid + i_ * 256;                                          \
            int wr_ = idx_ >> 5, wc_ = (idx_ & 31) << 2;                        \
            cp_async16(&Ws[buf][wr_ * 128 + wc_],                               \
                       W + (size_t)((kk) + wr_) * H_ + wc_);                    \
        }                                                                       \
        cp_commit();                                                            \
    } while (0)

    PROJ_STAGE(0, 0);
    for (int s = 0; s < 16; s++) {
        int buf = s & 1;
        if (s + 1 < 16) { PROJ_STAGE((s + 1) * 32, (s + 1) & 1); cp_wait<1>(); }
        else            { cp_wait<0>(); }
        __syncthreads();
#pragma unroll
        for (int k = 0; k < 32; k++) {
            const ulonglong2 bv = *(const ulonglong2*)&Ws[buf][k * 128 + tx * 4];
#pragma unroll
            for (int i = 0; i < 4; i++) {
                unsigned long long pa = bcast2(As[buf][(ty * 4 + i) * 32 + k]);
                fma2(acc[i][0], pa, bv.x);
                fma2(acc[i][1], pa, bv.y);
            }
        }
        __syncthreads();
    }
#undef PROJ_STAGE

#pragma unroll
    for (int i = 0; i < 4; i++) {
        float2 lo = unpack2(acc[i][0]);
        float2 hi = unpack2(acc[i][1]);
        float4 v = make_float4(lo.x, lo.y, hi.x, hi.y);
        *(float4*)(C + (size_t)(rowbase + ty * 4 + i) * H_ + tx * 4) = v;
    }
}

// ----------------------------------------------------------------------------
// Kernel 2: scores + softmax. Block: 128 threads = 4 warps, warp w owns q-row.
// Grid = B*Q/4 = 512. Scores kept in registers (32 per lane). kp chunks (32
// rows, padded stride 132) double-buffered via cp.async.
// ----------------------------------------------------------------------------
__global__ __launch_bounds__(128) void score_softmax_kernel(const float* __restrict__ wv_g)
{
    __shared__ float kp_sm[2][32 * 132];
    __shared__ float q_sm[4 * 128];
    __shared__ float w_sm[128];

    int tid = threadIdx.x;
    int w = tid >> 5;
    int l = tid & 31;

    int qb = blockIdx.x * 4;
    int b  = qb >> 9;
    int q0 = qb & 511;

    // stage 4 q-rows + w_v (plain stores; first __syncthreads covers them)
    {
        int r = tid >> 5, c = (tid & 31) << 2;
        *(float4*)&q_sm[r * 128 + c] =
            *(const float4*)&g_qp[(size_t)(b * Q_ + q0 + r) * H_ + c];
        if (tid < 32) *(float4*)&w_sm[tid * 4] = *(const float4*)&wv_g[tid * 4];
    }

    const float* kp_base = g_kp + (size_t)b * KK_ * H_;

#define KP_STAGE(ch, buf)                                                       \
    do {                                                                        \
        _Pragma("unroll")                                                       \
        for (int i_ = 0; i_ < 8; i_++) {                                        \
            int idx_ = tid + i_ * 128;                                          \
            int r_ = idx_ >> 5, c_ = (idx_ & 31) << 2;                          \
            cp_async16(&kp_sm[buf][r_ * 132 + c_],                              \
                       &kp_base[(size_t)((ch) * 32 + r_) * H_ + c_]);           \
        }                                                                       \
        cp_commit();                                                            \
    } while (0)

    float s[32];

    KP_STAGE(0, 0);
    for (int ch = 0; ch < 32; ch++) {
        int buf = ch & 1;
        if (ch + 1 < 32) { KP_STAGE(ch + 1, (ch + 1) & 1); cp_wait<1>(); }
        else             { cp_wait<0>(); }
        __syncthreads();

        const float4* kr = (const float4*)&kp_sm[buf][l * 132];
        const float4* qr = (const float4*)&q_sm[w * 128];
        const float4* wr = (const float4*)w_sm;
        float s0 = 0.f, s1 = 0.f, s2 = 0.f, s3 = 0.f;
#pragma unroll
        for (int h = 0; h < 32; h++) {
            float4 kv = kr[h];
            float4 qv = qr[h];
            float4 wv = wr[h];
            s0 += wv.x * tanh_fast(qv.x + kv.x);
            s1 += wv.y * tanh_fast(qv.y + kv.y);
            s2 += wv.z * tanh_fast(qv.z + kv.z);
            s3 += wv.w * tanh_fast(qv.w + kv.w);
        }
        s[ch] = (s0 + s1) + (s2 + s3);
        __syncthreads();
    }
#undef KP_STAGE

    // softmax: lane l holds scores for k = ch*32 + l
    float m = -1e30f;
#pragma unroll
    for (int j = 0; j < 32; j++) m = fmaxf(m, s[j]);
#pragma unroll
    for (int o = 16; o; o >>= 1) m = fmaxf(m, __shfl_xor_sync(0xffffffffu, m, o));
    float sum = 0.f;
#pragma unroll
    for (int j = 0; j < 32; j++) { s[j] = __expf(s[j] - m); sum += s[j]; }
#pragma unroll
    for (int o = 16; o; o >>= 1) sum += __shfl_xor_sync(0xffffffffu, sum, o);
    float inv = 1.0f / sum;

    float* arow = g_attn + (size_t)(b * Q_ + q0 + w) * KK_;
#pragma unroll
    for (int j = 0; j < 32; j++) arow[j * 32 + l] = s[j] * inv;
}

// ----------------------------------------------------------------------------
// Kernel 3: out[b] = attn[b] @ values[b].  M=512, N=512, Kd=1024 per batch.
// BM=BN=64, BK=32, 256 threads, micro 4x4 (2 f32x2 pairs), double-buffered.
// Grid (8, 8, 4) = 256 blocks.
// ----------------------------------------------------------------------------
__global__ __launch_bounds__(256) void av_gemm_kernel(
    const float* __restrict__ values, float* __restrict__ out)
{
    __shared__ float As[2][64 * 32];
    __shared__ float Bs[2][32 * 64];

    int b  = blockIdx.z;
    int mb = blockIdx.y * 64;
    int nb = blockIdx.x * 64;

    const float* Ab = g_attn + (size_t)b * Q_ * KK_;     // [512,1024]
    const float* Bb = values + (size_t)b * KK_ * DV_;    // [1024,512]
    float* Ob = out + (size_t)b * Q_ * DV_;

    int tid = threadIdx.x;
    int tx = tid & 15;     // cols nb + tx*4 .. +3
    int ty = tid >> 4;     // rows mb + ty*4 .. +3

    unsigned long long acc[4][2];
#pragma unroll
    for (int i = 0; i < 4; i++) { acc[i][0] = 0ull; acc[i][1] = 0ull; }

#define AV_STAGE(kk, buf)                                                       \
    do {                                                                        \
        _Pragma("unroll")                                                       \
        for (int i_ = 0; i_ < 2; i_++) {                                        \
            int idx_ = tid + i_ * 256;                                          \
            int r_ = idx_ >> 3, c_ = (idx_ & 7) << 2;                           \
            cp_async16(&As[buf][r_ * 32 + c_],                                  \
                       Ab + (size_t)(mb + r_) * KK_ + (kk) + c_);               \
        }                                                                       \
        _Pragma("unroll")                                                       \
        for (int i_ = 0; i_ < 2; i_++) {                                        \
            int idx_ = tid + i_ * 256;                                          \
            int r_ = idx_ >> 4, c_ = (idx_ & 15) << 2;                          \
            cp_async16(&Bs[buf][r_ * 64 + c_],                                  \
                       Bb + (size_t)((kk) + r_) * DV_ + nb + c_);               \
        }                                                                       \
        cp_commit();                                                            \
    } while (0)

    AV_STAGE(0, 0);
    for (int s = 0; s < 32; s++) {
        int buf = s & 1;
        if (s + 1 < 32) { AV_STAGE((s + 1) * 32, (s + 1) & 1); cp_wait<1>(); }
        else            { cp_wait<0>(); }
        __syncthreads();
#pragma unroll
        for (int k = 0; k < 32; k++) {
            const ulonglong2 bv = *(const ulonglong2*)&Bs[buf][k * 64 + tx * 4];
#pragma unroll
            for (int i = 0; i < 4; i++) {
                unsigned long long pa = bcast2(As[buf][(ty * 4 + i) * 32 + k]);
                fma2(acc[i][0], pa, bv.x);
                fma2(acc[i][1], pa, bv.y);
            }
        }
        __syncthreads();
    }
#undef AV_STAGE

#pragma unroll
    for (int i = 0; i < 4; i++) {
        float2 lo = unpack2(acc[i][0]);
        float2 hi = unpack2(acc[i][1]);
        float4 v = make_float4(lo.x, lo.y, hi.x, hi.y);
        *(float4*)(Ob + (size_t)(mb + ty * 4 + i) * DV_ + nb + tx * 4) = v;
    }
}

// ----------------------------------------------------------------------------
extern "C" void kernel_launch(void* const* d_in, const int* in_sizes, int n_in,
                              void* d_out, int out_size)
{
    const float* queries = (const float*)d_in[0];  // [4,512,512]
    const float* keys    = (const float*)d_in[1];  // [4,1024,512]
    const float* values  = (const float*)d_in[2];  // [4,1024,512]
    const float* W_q     = (const float*)d_in[3];  // [512,128]
    const float* W_k     = (const float*)d_in[4];  // [512,128]
    const float* w_v     = (const float*)d_in[5];  // [128]
    float* out = (float*)d_out;                    // [4,512,512]

    proj_kernel<<<192, 256>>>(queries, keys, W_q, W_k);
    score_softmax_kernel<<<512, 128>>>(w_v);
    dim3 g3(8, 8, 4);
    av_gemm_kernel<<<g3, 256>>>(values, out);
}